// round 1
// baseline (speedup 1.0000x reference)
#include <cuda_runtime.h>

// Problem constants
#define B_    64
#define S_    512
#define T_    32
#define H2_   1024      // hidden_size*2 (the "2H" feature dim)
#define ATT_  512
#define K_    1024      // GEMM K (== H2_)
#define WSTR_ 2048      // w1_w row stride (2*H2)

// Scratch (device globals — no allocation allowed)
__device__ float g_ht_mean[B_ * H2_];          // [B, 2H]
__device__ float g_c[B_ * ATT_];               // ht_mean @ W_m^T + bias
__device__ float g_beta_part[4][B_ * S_];      // per-N-tile partial beta
__device__ float g_alpha[B_ * S_];             // softmax weights

// ---------------------------------------------------------------------------
// A1: ht_mean[b,f] = mean_t ht[b,t,f]
// ---------------------------------------------------------------------------
__global__ void k_ht_mean(const float* __restrict__ ht) {
    int idx = blockIdx.x * 256 + threadIdx.x;          // b*H2 + f, < 65536
    int b = idx >> 10;
    int f = idx & (H2_ - 1);
    const float* p = ht + (size_t)b * T_ * H2_ + f;
    float s = 0.f;
#pragma unroll
    for (int t = 0; t < T_; ++t) s += p[(size_t)t * H2_];
    g_ht_mean[idx] = s * (1.0f / T_);
}

// ---------------------------------------------------------------------------
// A2: c[b,a] = dot(ht_mean[b,:], w1_w[a, 1024:2048]) + w1_b[a]
// one warp per (b,a)
// ---------------------------------------------------------------------------
__global__ void k_c(const float* __restrict__ w1_w,
                    const float* __restrict__ w1_b) {
    int warp = (blockIdx.x * blockDim.x + threadIdx.x) >> 5;
    int lane = threadIdx.x & 31;
    int b = warp >> 9;          // / 512
    int a = warp & 511;
    const float* wm = w1_w + (size_t)a * WSTR_ + H2_;
    const float* hm = g_ht_mean + b * H2_;
    float s = 0.f;
#pragma unroll 8
    for (int f = lane; f < H2_; f += 32) s += wm[f] * hm[f];
#pragma unroll
    for (int off = 16; off; off >>= 1)
        s += __shfl_down_sync(0xffffffffu, s, off);
    if (lane == 0) g_c[b * ATT_ + a] = s + w1_b[a];
}

// ---------------------------------------------------------------------------
// B: main fused GEMM:  z = h @ W_h^T + c ; beta_part = (u * tanh(z)) summed
// 128x128 block tile, BK=16, 8x8 per thread, 256 threads.
// ---------------------------------------------------------------------------
#define BM 128
#define BN 128
#define BK 16

__global__ __launch_bounds__(256) void k_gemm_beta(
    const float* __restrict__ h,
    const float* __restrict__ w1_w,
    const float* __restrict__ u_w)
{
    __shared__ float As[BK][BM];   // 8 KB
    __shared__ float Bs[BK][BN];   // 8 KB

    const int m0  = blockIdx.x * BM;     // row tile (b*512+s space)
    const int n0  = blockIdx.y * BN;     // attention-unit tile
    const int tid = threadIdx.x;
    const int tx  = tid & 15;
    const int ty  = tid >> 4;

    float acc[8][8];
#pragma unroll
    for (int i = 0; i < 8; ++i)
#pragma unroll
        for (int j = 0; j < 8; ++j) acc[i][j] = 0.f;

    for (int k0 = 0; k0 < K_; k0 += BK) {
        // Load A tile (128 rows x 16 k) and B tile, 2 float4 each per thread
#pragma unroll
        for (int it = 0; it < 2; ++it) {
            int l   = tid + it * 256;        // 0..511
            int row = l >> 2;                // 0..127
            int k4  = (l & 3) << 2;          // 0,4,8,12
            float4 va = *reinterpret_cast<const float4*>(
                h + (size_t)(m0 + row) * H2_ + k0 + k4);
            As[k4 + 0][row] = va.x;
            As[k4 + 1][row] = va.y;
            As[k4 + 2][row] = va.z;
            As[k4 + 3][row] = va.w;
            float4 vb = *reinterpret_cast<const float4*>(
                w1_w + (size_t)(n0 + row) * WSTR_ + k0 + k4);
            Bs[k4 + 0][row] = vb.x;
            Bs[k4 + 1][row] = vb.y;
            Bs[k4 + 2][row] = vb.z;
            Bs[k4 + 3][row] = vb.w;
        }
        __syncthreads();

#pragma unroll
        for (int kk = 0; kk < BK; ++kk) {
            float af[8], bf[8];
#pragma unroll
            for (int i = 0; i < 8; ++i) af[i] = As[kk][ty * 8 + i];
#pragma unroll
            for (int j = 0; j < 8; ++j) bf[j] = Bs[kk][tx * 8 + j];
#pragma unroll
            for (int i = 0; i < 8; ++i)
#pragma unroll
                for (int j = 0; j < 8; ++j)
                    acc[i][j] += af[i] * bf[j];
        }
        __syncthreads();
    }

    // Epilogue: z += c[b, n]; t = tanh(z); partial += u[n] * t
    const int b_idx = m0 >> 9;   // whole 128-row tile lies within one batch b
    float part[8];
#pragma unroll
    for (int i = 0; i < 8; ++i) {
        float p = 0.f;
#pragma unroll
        for (int j = 0; j < 8; ++j) {
            int n = n0 + tx * 8 + j;
            float z = acc[i][j] + g_c[b_idx * ATT_ + n];
            p += u_w[n] * tanhf(z);
        }
        part[i] = p;
    }
    __syncthreads();

    // reduce partials across the 16 tx lanes; reuse As storage (2048 floats)
    float (*red)[16] = reinterpret_cast<float(*)[16]>(&As[0][0]);
#pragma unroll
    for (int i = 0; i < 8; ++i) red[ty * 8 + i][tx] = part[i];
    __syncthreads();
    if (tid < 128) {
        float s = 0.f;
#pragma unroll
        for (int t = 0; t < 16; ++t) s += red[tid][t];
        g_beta_part[blockIdx.y][m0 + tid] = s;
    }
}

// ---------------------------------------------------------------------------
// C: masked softmax over S per batch row. One block per b, 512 threads.
// ---------------------------------------------------------------------------
__global__ void k_softmax(const int* __restrict__ h_mask) {
    int b = blockIdx.x;
    int s = threadIdx.x;
    int idx = b * S_ + s;
    float beta = g_beta_part[0][idx] + g_beta_part[1][idx] +
                 g_beta_part[2][idx] + g_beta_part[3][idx];
    bool valid = h_mask[idx] != 0;
    beta = valid ? beta : -1e20f;

    __shared__ float sm[512];
    sm[s] = beta;
    __syncthreads();
#pragma unroll
    for (int off = 256; off; off >>= 1) {
        if (s < off) sm[s] = fmaxf(sm[s], sm[s + off]);
        __syncthreads();
    }
    float mx = sm[0];
    __syncthreads();
    float e = __expf(beta - mx);
    sm[s] = e;
    __syncthreads();
#pragma unroll
    for (int off = 256; off; off >>= 1) {
        if (s < off) sm[s] += sm[s + off];
        __syncthreads();
    }
    g_alpha[idx] = e * (1.0f / sm[0]);
}

// ---------------------------------------------------------------------------
// D: out[b,d] = sum_s alpha[b,s] * h[b,s,d]
// grid (4, 64), 256 threads: each thread owns one d.
// ---------------------------------------------------------------------------
__global__ void k_out(const float* __restrict__ h, float* __restrict__ out) {
    int b = blockIdx.y;
    int d = blockIdx.x * 256 + threadIdx.x;
    const float* hp = h + (size_t)b * S_ * H2_ + d;
    const float* ap = g_alpha + b * S_;
    float acc = 0.f;
#pragma unroll 8
    for (int s = 0; s < S_; ++s) acc += ap[s] * hp[(size_t)s * H2_];
    out[b * H2_ + d] = acc;
}

// ---------------------------------------------------------------------------
extern "C" void kernel_launch(void* const* d_in, const int* in_sizes, int n_in,
                              void* d_out, int out_size) {
    const float* h      = (const float*)d_in[0];   // [64,512,1024]
    const int*   h_mask = (const int*)  d_in[1];   // [64,512]
    const float* ht     = (const float*)d_in[2];   // [64,32,1024]
    const float* w1_w   = (const float*)d_in[3];   // [512,2048]
    const float* w1_b   = (const float*)d_in[4];   // [512]
    const float* u_w    = (const float*)d_in[5];   // [1,512]
    float* out = (float*)d_out;                    // [64,1024]

    k_ht_mean<<<(B_ * H2_) / 256, 256>>>(ht);
    k_c<<<(B_ * ATT_) / 8, 256>>>(w1_w, w1_b);     // 8 warps/block
    k_gemm_beta<<<dim3((B_ * S_) / BM, ATT_ / BN), 256>>>(h, w1_w, u_w);
    k_softmax<<<B_, S_>>>(h_mask);
    k_out<<<dim3(H2_ / 256, B_), 256>>>(h, out);
}

// round 2
// speedup vs baseline: 2.8284x; 2.8284x over previous
#include <cuda_runtime.h>
#include <cstdint>

// Problem constants
#define B_    64
#define S_    512
#define T_    32
#define H2_   1024
#define ATT_  512
#define K_    1024
#define WSTR_ 2048

// GEMM tiling
#define BM 256
#define BN 128
#define BK 32
#define NITER (K_ / BK)          // 32
#define ASTRIDE 36               // BK + 4 pad  (stride % 32 == 4 -> conflict-free frags)
#define A_FLOATS (BM * ASTRIDE)  // 9216
#define B_FLOATS (BN * ASTRIDE)  // 4608
#define STAGE_FLOATS (A_FLOATS + B_FLOATS)   // 13824
#define SMEM_BYTES (2 * STAGE_FLOATS * 4)    // 110592

// Scratch
__device__ float g_ht_mean[B_ * H2_];
__device__ float g_c[B_ * ATT_];
__device__ float g_beta_part[4][B_ * S_];
__device__ float g_alpha[B_ * S_];

// ---------------------------------------------------------------------------
__global__ void k_ht_mean(const float* __restrict__ ht) {
    int idx = blockIdx.x * 256 + threadIdx.x;
    int b = idx >> 10;
    const float* p = ht + (size_t)b * T_ * H2_ + (idx & (H2_ - 1));
    float s = 0.f;
#pragma unroll
    for (int t = 0; t < T_; ++t) s += p[(size_t)t * H2_];
    g_ht_mean[idx] = s * (1.0f / T_);
}

__global__ void k_c(const float* __restrict__ w1_w,
                    const float* __restrict__ w1_b) {
    int warp = (blockIdx.x * blockDim.x + threadIdx.x) >> 5;
    int lane = threadIdx.x & 31;
    int b = warp >> 9;
    int a = warp & 511;
    const float* wm = w1_w + (size_t)a * WSTR_ + H2_;
    const float* hm = g_ht_mean + b * H2_;
    float s = 0.f;
#pragma unroll 8
    for (int f = lane; f < H2_; f += 32) s += wm[f] * hm[f];
#pragma unroll
    for (int off = 16; off; off >>= 1)
        s += __shfl_down_sync(0xffffffffu, s, off);
    if (lane == 0) g_c[b * ATT_ + a] = s + w1_b[a];
}

// ---------------------------------------------------------------------------
// Main fused GEMM on tensor cores (tf32 HMMA):
//   z = h @ W_h^T + c ;  beta_part = sum_n u[n] * tanh(z[:,n])
// ---------------------------------------------------------------------------
__device__ __forceinline__ void mma_tf32(float* d, const uint32_t* a,
                                         const uint32_t* b) {
    asm volatile(
        "mma.sync.aligned.m16n8k8.row.col.f32.tf32.tf32.f32 "
        "{%0,%1,%2,%3}, {%4,%5,%6,%7}, {%8,%9}, {%0,%1,%2,%3};\n"
        : "+f"(d[0]), "+f"(d[1]), "+f"(d[2]), "+f"(d[3])
        : "r"(a[0]), "r"(a[1]), "r"(a[2]), "r"(a[3]), "r"(b[0]), "r"(b[1]));
}

__device__ __forceinline__ void cp16(void* smem_dst, const void* gmem_src) {
    uint32_t dst = (uint32_t)__cvta_generic_to_shared(smem_dst);
    asm volatile("cp.async.cg.shared.global [%0], [%1], 16;\n"
                 :: "r"(dst), "l"(gmem_src));
}
#define CP_COMMIT asm volatile("cp.async.commit_group;\n" ::: "memory")
#define CP_WAIT0  asm volatile("cp.async.wait_group 0;\n" ::: "memory")

__global__ __launch_bounds__(512, 1) void k_gemm_beta(
    const float* __restrict__ h,
    const float* __restrict__ w1_w,
    const float* __restrict__ u_w)
{
    extern __shared__ float smem[];

    const int tid = threadIdx.x;
    const int lane = tid & 31;
    const int wid = tid >> 5;
    const int warp_m = wid >> 2;      // 0..3, 64 rows each
    const int warp_n = wid & 3;       // 0..3, 32 cols each
    const int r = lane >> 2;          // 0..7
    const int c = lane & 3;           // 0..3

    const int n0 = blockIdx.x * BN;   // 0..384
    const int m0 = blockIdx.y * BM;   // 0..32512
    const int b_idx = m0 >> 9;

    float acc[4][4][4];
#pragma unroll
    for (int i = 0; i < 4; ++i)
#pragma unroll
        for (int j = 0; j < 4; ++j)
#pragma unroll
            for (int q = 0; q < 4; ++q) acc[i][j][q] = 0.f;

    // stage loader: A = h rows, B = w1_w rows (first half of each row)
    auto load_stage = [&](int stage, int it) {
        float* sA = smem + stage * STAGE_FLOATS;
        float* sB = sA + A_FLOATS;
        const int kb = it * BK;
#pragma unroll
        for (int s = 0; s < 4; ++s) {            // A: 2048 chunks / 512 thr
            int id = tid + s * 512;
            int row = id >> 3, q = id & 7;
            cp16(sA + row * ASTRIDE + q * 4,
                 h + (size_t)(m0 + row) * H2_ + kb + q * 4);
        }
#pragma unroll
        for (int s = 0; s < 2; ++s) {            // B: 1024 chunks
            int id = tid + s * 512;
            int row = id >> 3, q = id & 7;
            cp16(sB + row * ASTRIDE + q * 4,
                 w1_w + (size_t)(n0 + row) * WSTR_ + kb + q * 4);
        }
    };

    load_stage(0, 0);
    CP_COMMIT;

    for (int it = 0; it < NITER; ++it) {
        CP_WAIT0;
        __syncthreads();
        if (it + 1 < NITER) {
            load_stage((it + 1) & 1, it + 1);
            CP_COMMIT;
        }
        const float* sA = smem + (it & 1) * STAGE_FLOATS;
        const float* sB = sA + A_FLOATS;
        const uint32_t* Abase = reinterpret_cast<const uint32_t*>(
            sA + (warp_m * 64 + r) * ASTRIDE + c);
        const uint32_t* Bbase = reinterpret_cast<const uint32_t*>(
            sB + (warp_n * 32 + r) * ASTRIDE + c);

#pragma unroll
        for (int ks = 0; ks < 4; ++ks) {
            uint32_t af[4][4], bf[4][2];
#pragma unroll
            for (int mf = 0; mf < 4; ++mf) {
                const uint32_t* p = Abase + mf * (16 * ASTRIDE) + ks * 8;
                af[mf][0] = p[0];
                af[mf][1] = p[8 * ASTRIDE];
                af[mf][2] = p[4];
                af[mf][3] = p[8 * ASTRIDE + 4];
            }
#pragma unroll
            for (int nf = 0; nf < 4; ++nf) {
                const uint32_t* p = Bbase + nf * (8 * ASTRIDE) + ks * 8;
                bf[nf][0] = p[0];
                bf[nf][1] = p[4];
            }
#pragma unroll
            for (int mf = 0; mf < 4; ++mf)
#pragma unroll
                for (int nf = 0; nf < 4; ++nf)
                    mma_tf32(acc[mf][nf], af[mf], bf[nf]);
        }
    }

    // ---- fused epilogue: beta partial = sum_n u[n]*tanh(z + c_b[n]) ----
    // per-thread columns: n = n0 + warp_n*32 + nf*8 + c*2 + j
    float uv[4][2], cv[4][2];
#pragma unroll
    for (int nf = 0; nf < 4; ++nf)
#pragma unroll
        for (int j = 0; j < 2; ++j) {
            int n = n0 + warp_n * 32 + nf * 8 + c * 2 + j;
            uv[nf][j] = u_w[n];
            cv[nf][j] = g_c[b_idx * ATT_ + n];
        }

    float part[4][2];
#pragma unroll
    for (int mf = 0; mf < 4; ++mf)
#pragma unroll
        for (int half = 0; half < 2; ++half) {
            float p = 0.f;
#pragma unroll
            for (int nf = 0; nf < 4; ++nf)
#pragma unroll
                for (int j = 0; j < 2; ++j) {
                    float z = acc[mf][nf][half * 2 + j] + cv[nf][j];
                    p += uv[nf][j] * tanhf(z);
                }
            part[mf][half] = p;
        }

    // reduce across the 4 lanes of the quad (same r, c = 0..3)
#pragma unroll
    for (int mf = 0; mf < 4; ++mf)
#pragma unroll
        for (int half = 0; half < 2; ++half) {
            float p = part[mf][half];
            p += __shfl_xor_sync(0xffffffffu, p, 1);
            p += __shfl_xor_sync(0xffffffffu, p, 2);
            part[mf][half] = p;
        }

    __syncthreads();   // done reading smem buffers; reuse for reduction
    float* red = smem;  // [256 rows][4 warp_n]
    if (c == 0) {
#pragma unroll
        for (int mf = 0; mf < 4; ++mf)
#pragma unroll
            for (int half = 0; half < 2; ++half) {
                int row = warp_m * 64 + mf * 16 + half * 8 + r;
                red[row * 4 + warp_n] = part[mf][half];
            }
    }
    __syncthreads();
    if (tid < BM) {
        float s = red[tid * 4 + 0] + red[tid * 4 + 1] +
                  red[tid * 4 + 2] + red[tid * 4 + 3];
        g_beta_part[blockIdx.x][m0 + tid] = s;
    }
}

// ---------------------------------------------------------------------------
__global__ void k_softmax(const int* __restrict__ h_mask) {
    int b = blockIdx.x;
    int s = threadIdx.x;
    int idx = b * S_ + s;
    float beta = g_beta_part[0][idx] + g_beta_part[1][idx] +
                 g_beta_part[2][idx] + g_beta_part[3][idx];
    bool valid = h_mask[idx] != 0;
    beta = valid ? beta : -1e20f;

    __shared__ float sm[512];
    sm[s] = beta;
    __syncthreads();
#pragma unroll
    for (int off = 256; off; off >>= 1) {
        if (s < off) sm[s] = fmaxf(sm[s], sm[s + off]);
        __syncthreads();
    }
    float mx = sm[0];
    __syncthreads();
    float e = __expf(beta - mx);
    sm[s] = e;
    __syncthreads();
#pragma unroll
    for (int off = 256; off; off >>= 1) {
        if (s < off) sm[s] += sm[s + off];
        __syncthreads();
    }
    g_alpha[idx] = e * (1.0f / sm[0]);
}

__global__ void k_out(const float* __restrict__ h, float* __restrict__ out) {
    int b = blockIdx.y;
    int d = blockIdx.x * 256 + threadIdx.x;
    const float* hp = h + (size_t)b * S_ * H2_ + d;
    const float* ap = g_alpha + b * S_;
    float acc = 0.f;
#pragma unroll 8
    for (int s = 0; s < S_; ++s) acc += ap[s] * hp[(size_t)s * H2_];
    out[b * H2_ + d] = acc;
}

// ---------------------------------------------------------------------------
extern "C" void kernel_launch(void* const* d_in, const int* in_sizes, int n_in,
                              void* d_out, int out_size) {
    const float* h      = (const float*)d_in[0];
    const int*   h_mask = (const int*)  d_in[1];
    const float* ht     = (const float*)d_in[2];
    const float* w1_w   = (const float*)d_in[3];
    const float* w1_b   = (const float*)d_in[4];
    const float* u_w    = (const float*)d_in[5];
    float* out = (float*)d_out;

    cudaFuncSetAttribute(k_gemm_beta,
                         cudaFuncAttributeMaxDynamicSharedMemorySize,
                         SMEM_BYTES);

    k_ht_mean<<<(B_ * H2_) / 256, 256>>>(ht);
    k_c<<<(B_ * ATT_) / 8, 256>>>(w1_w, w1_b);
    k_gemm_beta<<<dim3(ATT_ / BN, (B_ * S_) / BM), 512, SMEM_BYTES>>>(
        h, w1_w, u_w);
    k_softmax<<<B_, S_>>>(h_mask);
    k_out<<<dim3(H2_ / 256, B_), 256>>>(h, out);
}

// round 4
// speedup vs baseline: 3.3861x; 1.1972x over previous
#include <cuda_runtime.h>
#include <cuda_fp16.h>
#include <cstdint>

// Problem constants
#define B_    64
#define S_    512
#define T_    32
#define H2_   1024
#define ATT_  512
#define WSTR_ 2048

// GEMM tiling (fp16 mma.m16n8k16, fp32 accum)
#define BM 256
#define BN 128
#define BK 32
#define NIT (H2_ / BK)          // 32
#define RPW 20                  // uint32 per padded smem row (80 B)
#define ROWB 80
#define A_BYTES (BM * ROWB)     // 20480
#define B_BYTES (BN * ROWB)     // 10240
#define STAGE (A_BYTES + B_BYTES)          // 30720
#define GEMM_SMEM (2 * STAGE)              // 61440

// Scratch (device globals)
__device__ __half g_h16[(size_t)B_ * S_ * H2_];   // 64 MB fp16 copy of h
__device__ __half g_w16[ATT_ * H2_];              // fp16 copy of w1_w[:, :1024]
__device__ float  g_ht_mean[B_ * H2_];
__device__ float  g_c[B_ * ATT_];
__device__ float  g_beta_part[4][B_ * S_];
__device__ float  g_alpha[B_ * S_];

// ---------------------------------------------------------------------------
__device__ __forceinline__ uint32_t smem_u32(const void* p) {
    uint32_t a;
    asm("{ .reg .u64 t; cvta.to.shared.u64 t, %1; cvt.u32.u64 %0, t; }"
        : "=r"(a) : "l"(p));
    return a;
}
__device__ __forceinline__ void cp16(uint32_t smem_dst, const void* gsrc) {
    asm volatile("cp.async.cg.shared.global [%0], [%1], 16;\n"
                 :: "r"(smem_dst), "l"(gsrc));
}
#define CP_COMMIT asm volatile("cp.async.commit_group;\n" ::: "memory")
#define CP_WAIT0  asm volatile("cp.async.wait_group 0;\n" ::: "memory")

__device__ __forceinline__ void mma_f16(float* d, const uint32_t* a,
                                        const uint32_t* b) {
    asm volatile(
        "mma.sync.aligned.m16n8k16.row.col.f32.f16.f16.f32 "
        "{%0,%1,%2,%3}, {%4,%5,%6,%7}, {%8,%9}, {%0,%1,%2,%3};\n"
        : "+f"(d[0]), "+f"(d[1]), "+f"(d[2]), "+f"(d[3])
        : "r"(a[0]), "r"(a[1]), "r"(a[2]), "r"(a[3]), "r"(b[0]), "r"(b[1]));
}

// ---------------------------------------------------------------------------
// Converters: fp32 -> fp16 (h and w1_w first half)
// ---------------------------------------------------------------------------
__global__ void k_cvt_h(const float* __restrict__ h) {
    size_t i = ((size_t)blockIdx.x * 256 + threadIdx.x) * 8;
    float4 f0 = *reinterpret_cast<const float4*>(h + i);
    float4 f1 = *reinterpret_cast<const float4*>(h + i + 4);
    __half2 a = __floats2half2_rn(f0.x, f0.y);
    __half2 b = __floats2half2_rn(f0.z, f0.w);
    __half2 c = __floats2half2_rn(f1.x, f1.y);
    __half2 d = __floats2half2_rn(f1.z, f1.w);
    uint4 v;
    v.x = *reinterpret_cast<uint32_t*>(&a);
    v.y = *reinterpret_cast<uint32_t*>(&b);
    v.z = *reinterpret_cast<uint32_t*>(&c);
    v.w = *reinterpret_cast<uint32_t*>(&d);
    *reinterpret_cast<uint4*>(&g_h16[i]) = v;
}

__global__ void k_cvt_w(const float* __restrict__ w1_w) {
    size_t i = ((size_t)blockIdx.x * 256 + threadIdx.x) * 8;
    int row = (int)(i >> 10);
    int col = (int)(i & 1023);
    const float* src = w1_w + (size_t)row * WSTR_ + col;
    float4 f0 = *reinterpret_cast<const float4*>(src);
    float4 f1 = *reinterpret_cast<const float4*>(src + 4);
    __half2 a = __floats2half2_rn(f0.x, f0.y);
    __half2 b = __floats2half2_rn(f0.z, f0.w);
    __half2 c = __floats2half2_rn(f1.x, f1.y);
    __half2 d = __floats2half2_rn(f1.z, f1.w);
    uint4 v;
    v.x = *reinterpret_cast<uint32_t*>(&a);
    v.y = *reinterpret_cast<uint32_t*>(&b);
    v.z = *reinterpret_cast<uint32_t*>(&c);
    v.w = *reinterpret_cast<uint32_t*>(&d);
    *reinterpret_cast<uint4*>(&g_w16[i]) = v;
}

// ---------------------------------------------------------------------------
__global__ void k_ht_mean(const float* __restrict__ ht) {
    int idx = blockIdx.x * 256 + threadIdx.x;
    int b = idx >> 10;
    const float* p = ht + (size_t)b * T_ * H2_ + (idx & (H2_ - 1));
    float s = 0.f;
#pragma unroll
    for (int t = 0; t < T_; ++t) s += p[(size_t)t * H2_];
    g_ht_mean[idx] = s * (1.0f / T_);
}

__global__ void k_c(const float* __restrict__ w1_w,
                    const float* __restrict__ w1_b) {
    int warp = (blockIdx.x * blockDim.x + threadIdx.x) >> 5;
    int lane = threadIdx.x & 31;
    int b = warp >> 9;
    int a = warp & 511;
    const float* wm = w1_w + (size_t)a * WSTR_ + H2_;
    const float* hm = g_ht_mean + b * H2_;
    float s = 0.f;
#pragma unroll 8
    for (int f = lane; f < H2_; f += 32) s += wm[f] * hm[f];
#pragma unroll
    for (int off = 16; off; off >>= 1)
        s += __shfl_down_sync(0xffffffffu, s, off);
    if (lane == 0) g_c[b * ATT_ + a] = s + w1_b[a];
}

// ---------------------------------------------------------------------------
// Main fused GEMM (fp16 HMMA, fp32 accum):
//   z = h16 @ W16^T ; beta_part = sum_n u[n]*tanh(z + c[b,n])
// ---------------------------------------------------------------------------
__global__ __launch_bounds__(512, 1) void k_gemm_beta(
    const float* __restrict__ u_w)
{
    extern __shared__ char smem[];
    const uint32_t sb = smem_u32(smem);

    const int tid = threadIdx.x;
    const int lane = tid & 31;
    const int wid = tid >> 5;
    const int warp_m = wid >> 2;      // 0..3, 64 rows
    const int warp_n = wid & 3;       // 0..3, 32 cols
    const int r = lane >> 2;          // 0..7
    const int t = lane & 3;           // 0..3

    const int n0 = blockIdx.x * BN;
    const int m0 = blockIdx.y * BM;
    const int b_idx = m0 >> 9;

    float acc[4][4][4];
#pragma unroll
    for (int i = 0; i < 4; ++i)
#pragma unroll
        for (int j = 0; j < 4; ++j)
#pragma unroll
            for (int q = 0; q < 4; ++q) acc[i][j][q] = 0.f;

    auto load_stage = [&](int it) {
        const uint32_t base = sb + (uint32_t)(it & 1) * STAGE;
        const int kb = it * BK;
#pragma unroll
        for (int s = 0; s < 2; ++s) {          // A: 1024 16B chunks
            int id = tid + s * 512;
            int row = id >> 2, q = id & 3;
            cp16(base + (uint32_t)(row * ROWB + q * 16),
                 g_h16 + (size_t)(m0 + row) * H2_ + kb + q * 8);
        }
        {                                      // B: 512 chunks
            int row = tid >> 2, q = tid & 3;
            cp16(base + A_BYTES + (uint32_t)(row * ROWB + q * 16),
                 g_w16 + (size_t)(n0 + row) * H2_ + kb + q * 8);
        }
        CP_COMMIT;
    };

    load_stage(0);

    for (int it = 0; it < NIT; ++it) {
        CP_WAIT0;
        __syncthreads();
        if (it + 1 < NIT) load_stage(it + 1);

        const uint32_t* pA = reinterpret_cast<const uint32_t*>(
            smem + (it & 1) * STAGE);
        const uint32_t* pB = pA + A_BYTES / 4;

#pragma unroll
        for (int ks = 0; ks < 2; ++ks) {
            uint32_t af[4][4], bf[4][2];
#pragma unroll
            for (int mf = 0; mf < 4; ++mf) {
                const uint32_t* p =
                    pA + (warp_m * 64 + mf * 16 + r) * RPW + ks * 8 + t;
                af[mf][0] = p[0];
                af[mf][1] = p[8 * RPW];
                af[mf][2] = p[4];
                af[mf][3] = p[8 * RPW + 4];
            }
#pragma unroll
            for (int nf = 0; nf < 4; ++nf) {
                const uint32_t* p =
                    pB + (warp_n * 32 + nf * 8 + r) * RPW + ks * 8 + t;
                bf[nf][0] = p[0];
                bf[nf][1] = p[4];
            }
#pragma unroll
            for (int mf = 0; mf < 4; ++mf)
#pragma unroll
                for (int nf = 0; nf < 4; ++nf)
                    mma_f16(acc[mf][nf], af[mf], bf[nf]);
        }
        __syncthreads();
    }

    // ---- fused epilogue: beta partial = sum_n u[n]*tanh(z + c_b[n]) ----
    float uv[4][2], cv[4][2];
#pragma unroll
    for (int nf = 0; nf < 4; ++nf)
#pragma unroll
        for (int j = 0; j < 2; ++j) {
            int n = n0 + warp_n * 32 + nf * 8 + t * 2 + j;
            uv[nf][j] = u_w[n];
            cv[nf][j] = g_c[b_idx * ATT_ + n];
        }

    float part[4][2];
#pragma unroll
    for (int mf = 0; mf < 4; ++mf)
#pragma unroll
        for (int half = 0; half < 2; ++half) {
            float p = 0.f;
#pragma unroll
            for (int nf = 0; nf < 4; ++nf)
#pragma unroll
                for (int j = 0; j < 2; ++j) {
                    float z = acc[mf][nf][half * 2 + j] + cv[nf][j];
                    p += uv[nf][j] * tanhf(z);
                }
            part[mf][half] = p;
        }

#pragma unroll
    for (int mf = 0; mf < 4; ++mf)
#pragma unroll
        for (int half = 0; half < 2; ++half) {
            float p = part[mf][half];
            p += __shfl_xor_sync(0xffffffffu, p, 1);
            p += __shfl_xor_sync(0xffffffffu, p, 2);
            part[mf][half] = p;
        }

    __syncthreads();
    float* red = reinterpret_cast<float*>(smem);   // [256][4]
    if (t == 0) {
#pragma unroll
        for (int mf = 0; mf < 4; ++mf)
#pragma unroll
            for (int half = 0; half < 2; ++half) {
                int row = warp_m * 64 + mf * 16 + half * 8 + r;
                red[row * 4 + warp_n] = part[mf][half];
            }
    }
    __syncthreads();
    if (tid < BM) {
        float s = red[tid * 4 + 0] + red[tid * 4 + 1] +
                  red[tid * 4 + 2] + red[tid * 4 + 3];
        g_beta_part[blockIdx.x][m0 + tid] = s;
    }
}

// ---------------------------------------------------------------------------
__global__ void k_softmax(const int* __restrict__ h_mask) {
    int b = blockIdx.x;
    int s = threadIdx.x;
    int idx = b * S_ + s;
    float beta = g_beta_part[0][idx] + g_beta_part[1][idx] +
                 g_beta_part[2][idx] + g_beta_part[3][idx];
    bool valid = h_mask[idx] != 0;
    beta = valid ? beta : -1e20f;

    __shared__ float sm[512];
    sm[s] = beta;
    __syncthreads();
#pragma unroll
    for (int off = 256; off; off >>= 1) {
        if (s < off) sm[s] = fmaxf(sm[s], sm[s + off]);
        __syncthreads();
    }
    float mx = sm[0];
    __syncthreads();
    float e = __expf(beta - mx);
    sm[s] = e;
    __syncthreads();
#pragma unroll
    for (int off = 256; off; off >>= 1) {
        if (s < off) sm[s] += sm[s + off];
        __syncthreads();
    }
    g_alpha[idx] = e * (1.0f / sm[0]);
}

__global__ void k_out(const float* __restrict__ h, float* __restrict__ out) {
    int b = blockIdx.y;
    int d = blockIdx.x * 256 + threadIdx.x;
    const float* hp = h + (size_t)b * S_ * H2_ + d;
    const float* ap = g_alpha + b * S_;
    float acc = 0.f;
#pragma unroll 8
    for (int s = 0; s < S_; ++s) acc += ap[s] * hp[(size_t)s * H2_];
    out[b * H2_ + d] = acc;
}

// ---------------------------------------------------------------------------
extern "C" void kernel_launch(void* const* d_in, const int* in_sizes, int n_in,
                              void* d_out, int out_size) {
    const float* h      = (const float*)d_in[0];
    const int*   h_mask = (const int*)  d_in[1];
    const float* ht     = (const float*)d_in[2];
    const float* w1_w   = (const float*)d_in[3];
    const float* w1_b   = (const float*)d_in[4];
    const float* u_w    = (const float*)d_in[5];
    float* out = (float*)d_out;

    cudaFuncSetAttribute(k_gemm_beta,
                         cudaFuncAttributeMaxDynamicSharedMemorySize,
                         GEMM_SMEM);

    k_cvt_h<<<(B_ * S_ * H2_) / (256 * 8), 256>>>(h);
    k_cvt_w<<<(ATT_ * H2_) / (256 * 8), 256>>>(w1_w);
    k_ht_mean<<<(B_ * H2_) / 256, 256>>>(ht);
    k_c<<<(B_ * ATT_) / 8, 256>>>(w1_w, w1_b);
    k_gemm_beta<<<dim3(ATT_ / BN, (B_ * S_) / BM), 512, GEMM_SMEM>>>(u_w);
    k_softmax<<<B_, S_>>>(h_mask);
    k_out<<<dim3(H2_ / 256, B_), 256>>>(h, out);
}